// round 13
// baseline (speedup 1.0000x reference)
#include <cuda_runtime.h>
#include <math.h>

#define BB 16
#define NN 4096
#define CC 64
#define PP 1024
#define SS 32
#define NROWS (BB*PP*SS)   // 524288

__device__ float  d_featT[(size_t)BB*NN*CC];
__device__ float  d_xyzT[(size_t)BB*3*NN];
__device__ float  d_newxyz[BB*PP*3];
__device__ int    d_idx[BB*PP*SS];
__device__ float  d_y1[(size_t)NROWS*64];
__device__ float  d_y2[(size_t)NROWS*64];
__device__ float  d_m3[(size_t)BB*PP*128];
__device__ double g_s1[64], g_q1[64], g_s2[64], g_q2[64], g_s3[128], g_q3[128];
__device__ float  g_a1[64], g_c1[64], g_a2[64], g_c2[64], g_a3[128], g_c3[128];

__device__ __forceinline__ float sqdist(float ax,float ay,float az,float bx,float by,float bz){
    float dx=__fsub_rn(ax,bx), dy=__fsub_rn(ay,by), dz=__fsub_rn(az,bz);
    return __fadd_rn(__fadd_rn(__fmul_rn(dx,dx),__fmul_rn(dy,dy)),__fmul_rn(dz,dz));
}
__device__ __forceinline__ unsigned fkey(float f){
    unsigned u=__float_as_uint(f); return (u&0x80000000u)?~u:(u|0x80000000u);
}
__device__ __forceinline__ float finv(unsigned k){
    unsigned u=(k&0x80000000u)?(k&0x7fffffffu):~k; return __uint_as_float(u);
}
__device__ __forceinline__ unsigned long long pk2(float a,float b){
    unsigned long long r; asm("mov.b64 %0,{%1,%2};" : "=l"(r) : "f"(a),"f"(b)); return r;
}
__device__ __forceinline__ void upk2(unsigned long long v,float&a,float&b){
    asm("mov.b64 {%0,%1},%2;" : "=f"(a),"=f"(b) : "l"(v));
}
__device__ __forceinline__ unsigned long long add2(unsigned long long a,unsigned long long b){
    unsigned long long r; asm("add.rn.f32x2 %0,%1,%2;" : "=l"(r) : "l"(a),"l"(b)); return r;
}
__device__ __forceinline__ unsigned long long mul2(unsigned long long a,unsigned long long b){
    unsigned long long r; asm("mul.rn.f32x2 %0,%1,%2;" : "=l"(r) : "l"(a),"l"(b)); return r;
}
__device__ __forceinline__ unsigned f2tf(float f){
    unsigned r; asm("cvt.rna.tf32.f32 %0,%1;" : "=r"(r) : "f"(f)); return r;
}
__device__ __forceinline__ void mma_tf32(float* c, unsigned a0,unsigned a1,unsigned a2,unsigned a3,
                                         unsigned b0,unsigned b1){
    asm("mma.sync.aligned.m16n8k8.row.col.f32.tf32.tf32.f32 "
        "{%0,%1,%2,%3},{%4,%5,%6,%7},{%8,%9},{%0,%1,%2,%3};"
        : "+f"(c[0]),"+f"(c[1]),"+f"(c[2]),"+f"(c[3])
        : "r"(a0),"r"(a1),"r"(a2),"r"(a3),"r"(b0),"r"(b1));
}

__global__ void zero_stats(){
    int t=threadIdx.x;
    if(t<64){g_s1[t]=0.0;g_q1[t]=0.0;g_s2[t]=0.0;g_q2[t]=0.0;}
    if(t<128){g_s3[t]=0.0;g_q3[t]=0.0;}
}

__global__ void transpose_feat(const float* __restrict__ f){
    __shared__ float t[32][33];
    int b=blockIdx.z, c0=blockIdx.y*32, n0=blockIdx.x*32;
    const float* src=f+((size_t)b*CC+c0)*NN+n0;
#pragma unroll
    for(int k=0;k<32;k+=8)
        t[threadIdx.y+k][threadIdx.x]=src[(size_t)(threadIdx.y+k)*NN+threadIdx.x];
    __syncthreads();
    float* dst=d_featT+((size_t)b*NN+n0)*CC+c0;
#pragma unroll
    for(int k=0;k<32;k+=8)
        dst[(size_t)(threadIdx.y+k)*CC+threadIdx.x]=t[threadIdx.x][threadIdx.y+k];
}

__global__ __launch_bounds__(256) void xyz_soa(const float* __restrict__ xyz){
    __shared__ float s[768];
    int b=blockIdx.y, n0=blockIdx.x*256;
    const float* src=xyz+((size_t)b*NN+n0)*3;
    for(int k=threadIdx.x;k<768;k+=256) s[k]=src[k];
    __syncthreads();
    float* dst=d_xyzT+(size_t)b*3*NN;
    int n=n0+threadIdx.x;
    dst[n]      =s[threadIdx.x*3+0];
    dst[NN+n]   =s[threadIdx.x*3+1];
    dst[2*NN+n] =s[threadIdx.x*3+2];
}

// FPS: 256 thr x 16 pts, packed f32x2, REDUX argmax
__global__ __launch_bounds__(256,1) void fps_kernel(const float* __restrict__ xyz,
                                                    float* __restrict__ out_newxyz){
    int b=blockIdx.x, tid=threadIdx.x;
    int warp=tid>>5, lane=tid&31;
    const float* X=xyz+(size_t)b*NN*3;
    unsigned long long px2[8],py2[8],pz2[8];
    float dd[16];
#pragma unroll
    for(int jj=0;jj<8;jj++){
        int p0=tid+(2*jj)*256, p1=tid+(2*jj+1)*256;
        px2[jj]=pk2(X[p0*3+0],X[p1*3+0]);
        py2[jj]=pk2(X[p0*3+1],X[p1*3+1]);
        pz2[jj]=pk2(X[p0*3+2],X[p1*3+2]);
        dd[2*jj]=1e10f; dd[2*jj+1]=1e10f;
    }
    __shared__ unsigned s_d[2][8];
    __shared__ unsigned s_i[2][8];
    if(tid<8){ s_d[0][tid]=0u; s_d[1][tid]=0u; s_i[0][tid]=0xFFFFFFFFu; s_i[1][tid]=0xFFFFFFFFu; }
    float lx=__ldg(&X[0]), ly=__ldg(&X[1]), lz=__ldg(&X[2]);
    if(tid==0){
        float* o1=d_newxyz+(size_t)b*PP*3; o1[0]=lx;o1[1]=ly;o1[2]=lz;
        float* o2=out_newxyz+(size_t)b*PP*3; o2[0]=lx;o2[1]=ly;o2[2]=lz;
    }
    __syncthreads();
    for(int it=1; it<PP; it++){
        int p=it&1;
        unsigned long long nx=pk2(-lx,-lx), ny=pk2(-ly,-ly), nz=pk2(-lz,-lz);
#pragma unroll
        for(int jj=0;jj<8;jj++){
            unsigned long long dx=add2(px2[jj],nx);
            unsigned long long dy=add2(py2[jj],ny);
            unsigned long long dz=add2(pz2[jj],nz);
            unsigned long long s=add2(add2(mul2(dx,dx),mul2(dy,dy)),mul2(dz,dz));
            float d0,d1; upk2(s,d0,d1);
            dd[2*jj]=fminf(dd[2*jj],d0);
            dd[2*jj+1]=fminf(dd[2*jj+1],d1);
        }
        float m=dd[0];
#pragma unroll
        for(int j=1;j<16;j++) m=fmaxf(m,dd[j]);
        unsigned cand=0xFFFFFFFFu;
#pragma unroll
        for(int j=15;j>=0;j--) if(dd[j]==m) cand=tid+(unsigned)(j*256);
        unsigned mb=__float_as_uint(m);
        unsigned wmax=__reduce_max_sync(0xffffffffu, mb);
        unsigned wi=__reduce_min_sync(0xffffffffu, (mb==wmax)?cand:0xFFFFFFFFu);
        if(lane==0){ s_d[p][warp]=wmax; s_i[p][warp]=wi; }
        __syncthreads();
        unsigned dv=(lane<8)?s_d[p][lane]:0u;
        unsigned iv=(lane<8)?s_i[p][lane]:0xFFFFFFFFu;
        unsigned bmax=__reduce_max_sync(0xffffffffu, dv);
        unsigned widx=__reduce_min_sync(0xffffffffu, (dv==bmax)?iv:0xFFFFFFFFu);
        lx=__ldg(&X[widx*3+0]);
        ly=__ldg(&X[widx*3+1]);
        lz=__ldg(&X[widx*3+2]);
        if(tid==0){
            float* o1=d_newxyz+((size_t)b*PP+it)*3; o1[0]=lx;o1[1]=ly;o1[2]=lz;
            float* o2=out_newxyz+((size_t)b*PP+it)*3; o2[0]=lx;o2[1]=ly;o2[2]=lz;
        }
    }
}

__global__ __launch_bounds__(128) void ballq_kernel(){
    int warp=blockIdx.x*4+(threadIdx.x>>5);
    int lane=threadIdx.x&31;
    int b=warp>>10;
    const float* Xx=d_xyzT+(size_t)b*3*NN;
    const float* Xy=Xx+NN;
    const float* Xz=Xx+2*NN;
    float cx=d_newxyz[warp*3+0], cy=d_newxyz[warp*3+1], cz=d_newxyz[warp*3+2];
    int* out=d_idx+(size_t)warp*SS;
    const float R2=0.04f;
    int cnt=0, firstIdx=-1;
    for(int base=0; base<NN && cnt<SS; base+=32){
        int n=base+lane;
        bool in=sqdist(cx,cy,cz,Xx[n],Xy[n],Xz[n])<R2;
        unsigned m=__ballot_sync(0xffffffffu,in);
        if(firstIdx<0 && m) firstIdx=base+__ffs(m)-1;
        if(in){
            int pos=cnt+__popc(m&((1u<<lane)-1u));
            if(pos<SS) out[pos]=n;
        }
        cnt+=__popc(m);
    }
    int written=cnt<SS?cnt:SS;
    if(lane>=written) out[lane]=firstIdx;
}

__global__ void mkscale_kernel(const float* __restrict__ g, const float* __restrict__ bb,
                               int layer, int Cn){
    int o=threadIdx.x;
    if(o>=Cn) return;
    const double inv=1.0/(double)NROWS;
    double s,q;
    if(layer==1){s=g_s1[o];q=g_q1[o];}
    else if(layer==2){s=g_s2[o];q=g_q2[o];}
    else {s=g_s3[o];q=g_q3[o];}
    double m=s*inv, v=q*inv-m*m;
    double aa=(double)g[o]/sqrt(v+1e-5);
    float af=(float)aa, cf=(float)((double)bb[o]-m*aa);
    if(layer==1){g_a1[o]=af;g_c1[o]=cf;}
    else if(layer==2){g_a2[o]=af;g_c2[o]=cf;}
    else {g_a3[o]=af;g_c3[o]=cf;}
}

#define SMEM_L1T ((128*68 + 128*4 + 64*68 + 64*4 + 128)*4)
#define SMEM_L2T ((128*68 + 64*68 + 128)*4)
#define SMEM_L3T ((128*68 + 128*68 + 256 + 512)*4)

__global__ __launch_bounds__(512) void gemm_l1(const float* __restrict__ W1){
    extern __shared__ float dyn[];
    float (*sh_x)[68]=(float(*)[68])dyn;
    float (*sh_d)[4] =(float(*)[4])(dyn+128*68);
    float (*sh_w)[68]=(float(*)[68])(dyn+128*68+128*4);
    float (*sh_w3)[4]=(float(*)[4])(dyn+128*68+128*4+64*68);
    float* sh_sum=dyn+128*68+128*4+64*68+64*4;
    float* sh_sq =sh_sum+64;
    int tid=threadIdx.x, blk=blockIdx.x;
    for(int e=tid;e<64*67;e+=512){
        int o=e/67, c=e-o*67;
        if(c<3) sh_w3[o][c]=W1[e];
        else    sh_w[o][c-3]=W1[e];
    }
    if(tid<64){ sh_sum[tid]=0.f; sh_sq[tid]=0.f; }
    {
        int r=tid>>2, q=tid&3;
        int grp=blk*4+(r>>5);
        int b=grp>>10;
        int i=d_idx[(size_t)grp*SS+(r&31)];
        const float4* fr=(const float4*)(d_featT+((size_t)b*NN+i)*CC);
        float4* dst=(float4*)&sh_x[r][0];
#pragma unroll
        for(int k=0;k<4;k++) dst[q*4+k]=fr[q*4+k];
        if(q==0){
            const float* xt=d_xyzT+(size_t)b*3*NN;
            const float* cp=d_newxyz+(size_t)grp*3;
            sh_d[r][0]=__fsub_rn(xt[i],      cp[0]);
            sh_d[r][1]=__fsub_rn(xt[NN+i],   cp[1]);
            sh_d[r][2]=__fsub_rn(xt[2*NN+i], cp[2]);
        }
    }
    __syncthreads();
    int w=tid>>5, lane=tid&31, g=lane>>2, t=lane&3;
    int mt=w&7, nh=w>>3;
    int r0=mt*16;
    float acc[4][4];
#pragma unroll
    for(int nt=0;nt<4;nt++){acc[nt][0]=0;acc[nt][1]=0;acc[nt][2]=0;acc[nt][3]=0;}
#pragma unroll
    for(int kt=0;kt<8;kt++){
        int k0=kt*8;
        unsigned a0=f2tf(sh_x[r0+g  ][k0+t  ]);
        unsigned a1=f2tf(sh_x[r0+g+8][k0+t  ]);
        unsigned a2=f2tf(sh_x[r0+g  ][k0+t+4]);
        unsigned a3=f2tf(sh_x[r0+g+8][k0+t+4]);
#pragma unroll
        for(int nt=0;nt<4;nt++){
            int n0=nh*32+nt*8;
            unsigned b0=f2tf(sh_w[n0+g][k0+t  ]);
            unsigned b1=f2tf(sh_w[n0+g][k0+t+4]);
            mma_tf32(acc[nt], a0,a1,a2,a3, b0,b1);
        }
    }
    float dx0=sh_d[r0+g][0],   dy0=sh_d[r0+g][1],   dz0=sh_d[r0+g][2];
    float dx1=sh_d[r0+g+8][0], dy1=sh_d[r0+g+8][1], dz1=sh_d[r0+g+8][2];
#pragma unroll
    for(int nt=0;nt<4;nt++){
        int n0=nh*32+nt*8;
        int col=n0+2*t;
        float wa0=sh_w3[col][0],   wa1=sh_w3[col][1],   wa2=sh_w3[col][2];
        float wb0=sh_w3[col+1][0], wb1=sh_w3[col+1][1], wb2=sh_w3[col+1][2];
        acc[nt][0]+=dx0*wa0+dy0*wa1+dz0*wa2;
        acc[nt][1]+=dx0*wb0+dy0*wb1+dz0*wb2;
        acc[nt][2]+=dx1*wa0+dy1*wa1+dz1*wa2;
        acc[nt][3]+=dx1*wb0+dy1*wb1+dz1*wb2;
        float2 v0; v0.x=acc[nt][0]; v0.y=acc[nt][1];
        float2 v1; v1.x=acc[nt][2]; v1.y=acc[nt][3];
        *(float2*)(d_y1+((size_t)blk*128+r0+g  )*64+col)=v0;
        *(float2*)(d_y1+((size_t)blk*128+r0+g+8)*64+col)=v1;
        float s0=acc[nt][0]+acc[nt][2], s1=acc[nt][1]+acc[nt][3];
        float q0=acc[nt][0]*acc[nt][0]+acc[nt][2]*acc[nt][2];
        float q1=acc[nt][1]*acc[nt][1]+acc[nt][3]*acc[nt][3];
#pragma unroll
        for(int off=4;off<32;off<<=1){
            s0+=__shfl_xor_sync(0xffffffffu,s0,off);
            s1+=__shfl_xor_sync(0xffffffffu,s1,off);
            q0+=__shfl_xor_sync(0xffffffffu,q0,off);
            q1+=__shfl_xor_sync(0xffffffffu,q1,off);
        }
        if(lane<4){
            atomicAdd(&sh_sum[col],s0); atomicAdd(&sh_sum[col+1],s1);
            atomicAdd(&sh_sq[col],q0);  atomicAdd(&sh_sq[col+1],q1);
        }
    }
    __syncthreads();
    if(tid<64){ atomicAdd(&g_s1[tid],(double)sh_sum[tid]); atomicAdd(&g_q1[tid],(double)sh_sq[tid]); }
}

__global__ __launch_bounds__(512) void gemm_l2(const float* __restrict__ W2){
    extern __shared__ float dyn[];
    float (*sh_x)[68]=(float(*)[68])dyn;
    float (*sh_w)[68]=(float(*)[68])(dyn+128*68);
    float* sh_sum=dyn+128*68+64*68;
    float* sh_sq =sh_sum+64;
    int tid=threadIdx.x, blk=blockIdx.x;
    for(int e=tid;e<64*64;e+=512) sh_w[e>>6][e&63]=W2[e];
    if(tid<64){ sh_sum[tid]=0.f; sh_sq[tid]=0.f; }
    {
        int r=tid>>2, q=tid&3;
        const float4* src=(const float4*)(d_y1+((size_t)blk*128+r)*64+q*16);
#pragma unroll
        for(int k=0;k<4;k++){
            float4 v=src[k];
            int c0=q*16+k*4;
            sh_x[r][c0+0]=fmaxf(fmaf(g_a1[c0+0],v.x,g_c1[c0+0]),0.f);
            sh_x[r][c0+1]=fmaxf(fmaf(g_a1[c0+1],v.y,g_c1[c0+1]),0.f);
            sh_x[r][c0+2]=fmaxf(fmaf(g_a1[c0+2],v.z,g_c1[c0+2]),0.f);
            sh_x[r][c0+3]=fmaxf(fmaf(g_a1[c0+3],v.w,g_c1[c0+3]),0.f);
        }
    }
    __syncthreads();
    int w=tid>>5, lane=tid&31, g=lane>>2, t=lane&3;
    int mt=w&7, nh=w>>3;
    int r0=mt*16;
    float acc[4][4];
#pragma unroll
    for(int nt=0;nt<4;nt++){acc[nt][0]=0;acc[nt][1]=0;acc[nt][2]=0;acc[nt][3]=0;}
#pragma unroll
    for(int kt=0;kt<8;kt++){
        int k0=kt*8;
        unsigned a0=f2tf(sh_x[r0+g  ][k0+t  ]);
        unsigned a1=f2tf(sh_x[r0+g+8][k0+t  ]);
        unsigned a2=f2tf(sh_x[r0+g  ][k0+t+4]);
        unsigned a3=f2tf(sh_x[r0+g+8][k0+t+4]);
#pragma unroll
        for(int nt=0;nt<4;nt++){
            int n0=nh*32+nt*8;
            unsigned b0=f2tf(sh_w[n0+g][k0+t  ]);
            unsigned b1=f2tf(sh_w[n0+g][k0+t+4]);
            mma_tf32(acc[nt], a0,a1,a2,a3, b0,b1);
        }
    }
#pragma unroll
    for(int nt=0;nt<4;nt++){
        int n0=nh*32+nt*8;
        int col=n0+2*t;
        float2 v0; v0.x=acc[nt][0]; v0.y=acc[nt][1];
        float2 v1; v1.x=acc[nt][2]; v1.y=acc[nt][3];
        *(float2*)(d_y2+((size_t)blk*128+r0+g  )*64+col)=v0;
        *(float2*)(d_y2+((size_t)blk*128+r0+g+8)*64+col)=v1;
        float s0=acc[nt][0]+acc[nt][2], s1=acc[nt][1]+acc[nt][3];
        float q0=acc[nt][0]*acc[nt][0]+acc[nt][2]*acc[nt][2];
        float q1=acc[nt][1]*acc[nt][1]+acc[nt][3]*acc[nt][3];
#pragma unroll
        for(int off=4;off<32;off<<=1){
            s0+=__shfl_xor_sync(0xffffffffu,s0,off);
            s1+=__shfl_xor_sync(0xffffffffu,s1,off);
            q0+=__shfl_xor_sync(0xffffffffu,q0,off);
            q1+=__shfl_xor_sync(0xffffffffu,q1,off);
        }
        if(lane<4){
            atomicAdd(&sh_sum[col],s0); atomicAdd(&sh_sum[col+1],s1);
            atomicAdd(&sh_sq[col],q0);  atomicAdd(&sh_sq[col+1],q1);
        }
    }
    __syncthreads();
    if(tid<64){ atomicAdd(&g_s2[tid],(double)sh_sum[tid]); atomicAdd(&g_q2[tid],(double)sh_sq[tid]); }
}

__global__ __launch_bounds__(512) void gemm_l3(const float* __restrict__ W3){
    extern __shared__ float dyn[];
    float (*sh_x)[68]=(float(*)[68])dyn;
    float (*sh_w)[68]=(float(*)[68])(dyn+128*68);
    float* sh_sum=dyn+128*68+128*68;
    float* sh_sq =sh_sum+128;
    unsigned* sh_max=(unsigned*)(sh_sq+128);
    int tid=threadIdx.x, blk=blockIdx.x;
    for(int e=tid;e<128*64;e+=512) sh_w[e>>6][e&63]=W3[e];
    if(tid<128){ sh_sum[tid]=0.f; sh_sq[tid]=0.f; }
    if(tid<512) sh_max[tid]=0u;
    {
        int r=tid>>2, q=tid&3;
        const float4* src=(const float4*)(d_y2+((size_t)blk*128+r)*64+q*16);
#pragma unroll
        for(int k=0;k<4;k++){
            float4 v=src[k];
            int c0=q*16+k*4;
            sh_x[r][c0+0]=fmaxf(fmaf(g_a2[c0+0],v.x,g_c2[c0+0]),0.f);
            sh_x[r][c0+1]=fmaxf(fmaf(g_a2[c0+1],v.y,g_c2[c0+1]),0.f);
            sh_x[r][c0+2]=fmaxf(fmaf(g_a2[c0+2],v.z,g_c2[c0+2]),0.f);
            sh_x[r][c0+3]=fmaxf(fmaf(g_a2[c0+3],v.w,g_c2[c0+3]),0.f);
        }
    }
    __syncthreads();
    int w=tid>>5, lane=tid&31, g=lane>>2, t=lane&3;
    int mt=w&7, nh=w>>3;
    int r0=mt*16;
    int grp=mt>>1;
    float acc[8][4];
#pragma unroll
    for(int nt=0;nt<8;nt++){acc[nt][0]=0;acc[nt][1]=0;acc[nt][2]=0;acc[nt][3]=0;}
#pragma unroll
    for(int kt=0;kt<8;kt++){
        int k0=kt*8;
        unsigned a0=f2tf(sh_x[r0+g  ][k0+t  ]);
        unsigned a1=f2tf(sh_x[r0+g+8][k0+t  ]);
        unsigned a2=f2tf(sh_x[r0+g  ][k0+t+4]);
        unsigned a3=f2tf(sh_x[r0+g+8][k0+t+4]);
#pragma unroll
        for(int nt=0;nt<8;nt++){
            int n0=nh*64+nt*8;
            unsigned b0=f2tf(sh_w[n0+g][k0+t  ]);
            unsigned b1=f2tf(sh_w[n0+g][k0+t+4]);
            mma_tf32(acc[nt], a0,a1,a2,a3, b0,b1);
        }
    }
#pragma unroll
    for(int nt=0;nt<8;nt++){
        int n0=nh*64+nt*8;
        int col=n0+2*t;
        float s0=acc[nt][0]+acc[nt][2], s1=acc[nt][1]+acc[nt][3];
        float q0=acc[nt][0]*acc[nt][0]+acc[nt][2]*acc[nt][2];
        float q1=acc[nt][1]*acc[nt][1]+acc[nt][3]*acc[nt][3];
        float m0=fmaxf(acc[nt][0],acc[nt][2]), m1=fmaxf(acc[nt][1],acc[nt][3]);
#pragma unroll
        for(int off=4;off<32;off<<=1){
            s0+=__shfl_xor_sync(0xffffffffu,s0,off);
            s1+=__shfl_xor_sync(0xffffffffu,s1,off);
            q0+=__shfl_xor_sync(0xffffffffu,q0,off);
            q1+=__shfl_xor_sync(0xffffffffu,q1,off);
            m0=fmaxf(m0,__shfl_xor_sync(0xffffffffu,m0,off));
            m1=fmaxf(m1,__shfl_xor_sync(0xffffffffu,m1,off));
        }
        if(lane<4){
            atomicAdd(&sh_sum[col],s0); atomicAdd(&sh_sum[col+1],s1);
            atomicAdd(&sh_sq[col],q0);  atomicAdd(&sh_sq[col+1],q1);
            atomicMax(&sh_max[grp*128+col],fkey(m0));
            atomicMax(&sh_max[grp*128+col+1],fkey(m1));
        }
    }
    __syncthreads();
    if(tid<128){
        atomicAdd(&g_s3[tid],(double)sh_sum[tid]);
        atomicAdd(&g_q3[tid],(double)sh_sq[tid]);
    }
    if(tid<512)
        d_m3[((size_t)blk*4+(tid>>7))*128+(tid&127)]=finv(sh_max[tid]);
}

__global__ void final_kernel(float* __restrict__ outf){
    __shared__ float t[32][33];
    int b=blockIdx.z, o0=blockIdx.y*32, p0=blockIdx.x*32;
#pragma unroll
    for(int k=0;k<32;k+=8){
        int p=p0+threadIdx.y+k, o=o0+threadIdx.x;
        float v=d_m3[((size_t)b*PP+p)*128+o];
        t[threadIdx.y+k][threadIdx.x]=fmaxf(fmaf(g_a3[o],v,g_c3[o]),0.f);
    }
    __syncthreads();
#pragma unroll
    for(int k=0;k<32;k+=8){
        int o=o0+threadIdx.y+k;
        outf[((size_t)b*128+o)*PP+p0+threadIdx.x]=t[threadIdx.x][threadIdx.y+k];
    }
}

extern "C" void kernel_launch(void* const* d_in, const int* in_sizes, int n_in,
                              void* d_out, int out_size){
    const float* xyz =(const float*)d_in[0];
    const float* feat=(const float*)d_in[1];
    const float* W1  =(const float*)d_in[2];
    const float* g1  =(const float*)d_in[3];
    const float* b1  =(const float*)d_in[4];
    const float* W2  =(const float*)d_in[5];
    const float* g2  =(const float*)d_in[6];
    const float* b2  =(const float*)d_in[7];
    const float* W3  =(const float*)d_in[8];
    const float* g3  =(const float*)d_in[9];
    const float* b3  =(const float*)d_in[10];
    float* out=(float*)d_out;
    float* out_newxyz=out;
    float* out_feat  =out+(size_t)BB*PP*3;

    static int init_done=0;
    static cudaStream_t s2;
    static cudaEvent_t ev_fork, ev_join;
    if(!init_done){
        cudaFuncSetAttribute(gemm_l1, cudaFuncAttributeMaxDynamicSharedMemorySize, SMEM_L1T);
        cudaFuncSetAttribute(gemm_l2, cudaFuncAttributeMaxDynamicSharedMemorySize, SMEM_L2T);
        cudaFuncSetAttribute(gemm_l3, cudaFuncAttributeMaxDynamicSharedMemorySize, SMEM_L3T);
        cudaStreamCreateWithFlags(&s2, cudaStreamNonBlocking);
        cudaEventCreateWithFlags(&ev_fork, cudaEventDisableTiming);
        cudaEventCreateWithFlags(&ev_join, cudaEventDisableTiming);
        init_done=1;
    }

    // fork: transpose_feat runs on s2 concurrently with fps on the main stream
    cudaEventRecord(ev_fork, 0);
    cudaStreamWaitEvent(s2, ev_fork, 0);

    zero_stats<<<1,128>>>();
    {
        dim3 g(NN/256, BB);
        xyz_soa<<<g,256>>>(xyz);
    }
    {
        dim3 g(NN/32, CC/32, BB), b(32,8);
        transpose_feat<<<g,b,0,s2>>>(feat);
    }
    cudaEventRecord(ev_join, s2);

    fps_kernel<<<BB,256>>>(xyz, out_newxyz);
    ballq_kernel<<<(BB*PP)/4,128>>>();

    // join before gemm_l1 (needs d_featT)
    cudaStreamWaitEvent(0, ev_join, 0);

    gemm_l1<<<NROWS/128,512,SMEM_L1T>>>(W1);
    mkscale_kernel<<<1,128>>>(g1,b1,1,64);
    gemm_l2<<<NROWS/128,512,SMEM_L2T>>>(W2);
    mkscale_kernel<<<1,128>>>(g2,b2,2,64);
    gemm_l3<<<NROWS/128,512,SMEM_L3T>>>(W3);
    mkscale_kernel<<<1,128>>>(g3,b3,3,128);
    {
        dim3 g(PP/32, 128/32, BB), b(32,8);
        final_kernel<<<g,b>>>(out_feat);
    }
}

// round 14
// speedup vs baseline: 1.1754x; 1.1754x over previous
#include <cuda_runtime.h>
#include <cuda_fp16.h>
#include <math.h>

#define BB 16
#define NN 4096
#define CC 64
#define PP 1024
#define SS 32
#define NROWS (BB*PP*SS)   // 524288

__device__ __half  d_featTh[(size_t)BB*NN*CC];
__device__ float   d_xyzT[(size_t)BB*3*NN];
__device__ float   d_newxyz[BB*PP*3];
__device__ int     d_idx[BB*PP*SS];
__device__ __half  d_y1h[(size_t)NROWS*64];
__device__ __half  d_y2h[(size_t)NROWS*64];
__device__ float   d_m3[(size_t)BB*PP*128];
__device__ double  g_s1[64], g_q1[64], g_s2[64], g_q2[64], g_s3[128], g_q3[128];
__device__ float   g_a1[64], g_c1[64], g_a2[64], g_c2[64], g_a3[128], g_c3[128];

__device__ __forceinline__ float sqdist(float ax,float ay,float az,float bx,float by,float bz){
    float dx=__fsub_rn(ax,bx), dy=__fsub_rn(ay,by), dz=__fsub_rn(az,bz);
    return __fadd_rn(__fadd_rn(__fmul_rn(dx,dx),__fmul_rn(dy,dy)),__fmul_rn(dz,dz));
}
__device__ __forceinline__ unsigned fkey(float f){
    unsigned u=__float_as_uint(f); return (u&0x80000000u)?~u:(u|0x80000000u);
}
__device__ __forceinline__ float finv(unsigned k){
    unsigned u=(k&0x80000000u)?(k&0x7fffffffu):~k; return __uint_as_float(u);
}
__device__ __forceinline__ unsigned long long pk2(float a,float b){
    unsigned long long r; asm("mov.b64 %0,{%1,%2};" : "=l"(r) : "f"(a),"f"(b)); return r;
}
__device__ __forceinline__ void upk2(unsigned long long v,float&a,float&b){
    asm("mov.b64 {%0,%1},%2;" : "=f"(a),"=f"(b) : "l"(v));
}
__device__ __forceinline__ unsigned long long add2(unsigned long long a,unsigned long long b){
    unsigned long long r; asm("add.rn.f32x2 %0,%1,%2;" : "=l"(r) : "l"(a),"l"(b)); return r;
}
__device__ __forceinline__ unsigned long long mul2(unsigned long long a,unsigned long long b){
    unsigned long long r; asm("mul.rn.f32x2 %0,%1,%2;" : "=l"(r) : "l"(a),"l"(b)); return r;
}
__device__ __forceinline__ unsigned f2tf(float f){
    unsigned r; asm("cvt.rna.tf32.f32 %0,%1;" : "=r"(r) : "f"(f)); return r;
}
__device__ __forceinline__ void mma_tf32(float* c, unsigned a0,unsigned a1,unsigned a2,unsigned a3,
                                         unsigned b0,unsigned b1){
    asm("mma.sync.aligned.m16n8k8.row.col.f32.tf32.tf32.f32 "
        "{%0,%1,%2,%3},{%4,%5,%6,%7},{%8,%9},{%0,%1,%2,%3};"
        : "+f"(c[0]),"+f"(c[1]),"+f"(c[2]),"+f"(c[3])
        : "r"(a0),"r"(a1),"r"(a2),"r"(a3),"r"(b0),"r"(b1));
}

__global__ void zero_stats(){
    int t=threadIdx.x;
    if(t<64){g_s1[t]=0.0;g_q1[t]=0.0;g_s2[t]=0.0;g_q2[t]=0.0;}
    if(t<128){g_s3[t]=0.0;g_q3[t]=0.0;}
}

// features (B,64,N) fp32 -> (B,N,64) fp16
__global__ void transpose_feat(const float* __restrict__ f){
    __shared__ float t[32][33];
    int b=blockIdx.z, c0=blockIdx.y*32, n0=blockIdx.x*32;
    const float* src=f+((size_t)b*CC+c0)*NN+n0;
#pragma unroll
    for(int k=0;k<32;k+=8)
        t[threadIdx.y+k][threadIdx.x]=src[(size_t)(threadIdx.y+k)*NN+threadIdx.x];
    __syncthreads();
    __half* dst=d_featTh+((size_t)b*NN+n0)*CC+c0;
#pragma unroll
    for(int k=0;k<32;k+=8)
        dst[(size_t)(threadIdx.y+k)*CC+threadIdx.x]=__float2half_rn(t[threadIdx.x][threadIdx.y+k]);
}

__global__ __launch_bounds__(256) void xyz_soa(const float* __restrict__ xyz){
    __shared__ float s[768];
    int b=blockIdx.y, n0=blockIdx.x*256;
    const float* src=xyz+((size_t)b*NN+n0)*3;
    for(int k=threadIdx.x;k<768;k+=256) s[k]=src[k];
    __syncthreads();
    float* dst=d_xyzT+(size_t)b*3*NN;
    int n=n0+threadIdx.x;
    dst[n]      =s[threadIdx.x*3+0];
    dst[NN+n]   =s[threadIdx.x*3+1];
    dst[2*NN+n] =s[threadIdx.x*3+2];
}

// FPS: 256 thr x 16 pts, packed f32x2, REDUX argmax
__global__ __launch_bounds__(256,1) void fps_kernel(const float* __restrict__ xyz,
                                                    float* __restrict__ out_newxyz){
    int b=blockIdx.x, tid=threadIdx.x;
    int warp=tid>>5, lane=tid&31;
    const float* X=xyz+(size_t)b*NN*3;
    unsigned long long px2[8],py2[8],pz2[8];
    float dd[16];
#pragma unroll
    for(int jj=0;jj<8;jj++){
        int p0=tid+(2*jj)*256, p1=tid+(2*jj+1)*256;
        px2[jj]=pk2(X[p0*3+0],X[p1*3+0]);
        py2[jj]=pk2(X[p0*3+1],X[p1*3+1]);
        pz2[jj]=pk2(X[p0*3+2],X[p1*3+2]);
        dd[2*jj]=1e10f; dd[2*jj+1]=1e10f;
    }
    __shared__ unsigned s_d[2][8];
    __shared__ unsigned s_i[2][8];
    if(tid<8){ s_d[0][tid]=0u; s_d[1][tid]=0u; s_i[0][tid]=0xFFFFFFFFu; s_i[1][tid]=0xFFFFFFFFu; }
    float lx=__ldg(&X[0]), ly=__ldg(&X[1]), lz=__ldg(&X[2]);
    if(tid==0){
        float* o1=d_newxyz+(size_t)b*PP*3; o1[0]=lx;o1[1]=ly;o1[2]=lz;
        float* o2=out_newxyz+(size_t)b*PP*3; o2[0]=lx;o2[1]=ly;o2[2]=lz;
    }
    __syncthreads();
    for(int it=1; it<PP; it++){
        int p=it&1;
        unsigned long long nx=pk2(-lx,-lx), ny=pk2(-ly,-ly), nz=pk2(-lz,-lz);
#pragma unroll
        for(int jj=0;jj<8;jj++){
            unsigned long long dx=add2(px2[jj],nx);
            unsigned long long dy=add2(py2[jj],ny);
            unsigned long long dz=add2(pz2[jj],nz);
            unsigned long long s=add2(add2(mul2(dx,dx),mul2(dy,dy)),mul2(dz,dz));
            float d0,d1; upk2(s,d0,d1);
            dd[2*jj]=fminf(dd[2*jj],d0);
            dd[2*jj+1]=fminf(dd[2*jj+1],d1);
        }
        float m=dd[0];
#pragma unroll
        for(int j=1;j<16;j++) m=fmaxf(m,dd[j]);
        unsigned cand=0xFFFFFFFFu;
#pragma unroll
        for(int j=15;j>=0;j--) if(dd[j]==m) cand=tid+(unsigned)(j*256);
        unsigned mb=__float_as_uint(m);
        unsigned wmax=__reduce_max_sync(0xffffffffu, mb);
        unsigned wi=__reduce_min_sync(0xffffffffu, (mb==wmax)?cand:0xFFFFFFFFu);
        if(lane==0){ s_d[p][warp]=wmax; s_i[p][warp]=wi; }
        __syncthreads();
        unsigned dv=(lane<8)?s_d[p][lane]:0u;
        unsigned iv=(lane<8)?s_i[p][lane]:0xFFFFFFFFu;
        unsigned bmax=__reduce_max_sync(0xffffffffu, dv);
        unsigned widx=__reduce_min_sync(0xffffffffu, (dv==bmax)?iv:0xFFFFFFFFu);
        lx=__ldg(&X[widx*3+0]);
        ly=__ldg(&X[widx*3+1]);
        lz=__ldg(&X[widx*3+2]);
        if(tid==0){
            float* o1=d_newxyz+((size_t)b*PP+it)*3; o1[0]=lx;o1[1]=ly;o1[2]=lz;
            float* o2=out_newxyz+((size_t)b*PP+it)*3; o2[0]=lx;o2[1]=ly;o2[2]=lz;
        }
    }
}

__global__ __launch_bounds__(128) void ballq_kernel(){
    int warp=blockIdx.x*4+(threadIdx.x>>5);
    int lane=threadIdx.x&31;
    int b=warp>>10;
    const float* Xx=d_xyzT+(size_t)b*3*NN;
    const float* Xy=Xx+NN;
    const float* Xz=Xx+2*NN;
    float cx=d_newxyz[warp*3+0], cy=d_newxyz[warp*3+1], cz=d_newxyz[warp*3+2];
    int* out=d_idx+(size_t)warp*SS;
    const float R2=0.04f;
    int cnt=0, firstIdx=-1;
    for(int base=0; base<NN && cnt<SS; base+=32){
        int n=base+lane;
        bool in=sqdist(cx,cy,cz,Xx[n],Xy[n],Xz[n])<R2;
        unsigned m=__ballot_sync(0xffffffffu,in);
        if(firstIdx<0 && m) firstIdx=base+__ffs(m)-1;
        if(in){
            int pos=cnt+__popc(m&((1u<<lane)-1u));
            if(pos<SS) out[pos]=n;
        }
        cnt+=__popc(m);
    }
    int written=cnt<SS?cnt:SS;
    if(lane>=written) out[lane]=firstIdx;
}

__global__ void mkscale_kernel(const float* __restrict__ g, const float* __restrict__ bb,
                               int layer, int Cn){
    int o=threadIdx.x;
    if(o>=Cn) return;
    const double inv=1.0/(double)NROWS;
    double s,q;
    if(layer==1){s=g_s1[o];q=g_q1[o];}
    else if(layer==2){s=g_s2[o];q=g_q2[o];}
    else {s=g_s3[o];q=g_q3[o];}
    double m=s*inv, v=q*inv-m*m;
    double aa=(double)g[o]/sqrt(v+1e-5);
    float af=(float)aa, cf=(float)((double)bb[o]-m*aa);
    if(layer==1){g_a1[o]=af;g_c1[o]=cf;}
    else if(layer==2){g_a2[o]=af;g_c2[o]=cf;}
    else {g_a3[o]=af;g_c3[o]=cf;}
}

#define SMEM_L1T ((128*68 + 128*4 + 64*68 + 64*4 + 128)*4)
#define SMEM_L2T ((128*68 + 64*68 + 128)*4)
#define SMEM_L3T ((128*68 + 128*68 + 256 + 512)*4)

// unpack 8 halfs (uint4) -> BN+ReLU -> sh row
__device__ __forceinline__ void h8_bn(uint4 u,float* dst,const float* ga,const float* gc,int c0){
    float2 f;
    f=__half22float2(*(__half2*)&u.x);
    dst[0]=fmaxf(fmaf(ga[c0+0],f.x,gc[c0+0]),0.f);
    dst[1]=fmaxf(fmaf(ga[c0+1],f.y,gc[c0+1]),0.f);
    f=__half22float2(*(__half2*)&u.y);
    dst[2]=fmaxf(fmaf(ga[c0+2],f.x,gc[c0+2]),0.f);
    dst[3]=fmaxf(fmaf(ga[c0+3],f.y,gc[c0+3]),0.f);
    f=__half22float2(*(__half2*)&u.z);
    dst[4]=fmaxf(fmaf(ga[c0+4],f.x,gc[c0+4]),0.f);
    dst[5]=fmaxf(fmaf(ga[c0+5],f.y,gc[c0+5]),0.f);
    f=__half22float2(*(__half2*)&u.w);
    dst[6]=fmaxf(fmaf(ga[c0+6],f.x,gc[c0+6]),0.f);
    dst[7]=fmaxf(fmaf(ga[c0+7],f.y,gc[c0+7]),0.f);
}

// layer1: fp16 gather, tf32 mma K=64 + fp32 xyz epilogue, fp16 y1 out, stats
__global__ __launch_bounds__(512) void gemm_l1(const float* __restrict__ W1){
    extern __shared__ float dyn[];
    float (*sh_x)[68]=(float(*)[68])dyn;
    float (*sh_d)[4] =(float(*)[4])(dyn+128*68);
    float (*sh_w)[68]=(float(*)[68])(dyn+128*68+128*4);
    float (*sh_w3)[4]=(float(*)[4])(dyn+128*68+128*4+64*68);
    float* sh_sum=dyn+128*68+128*4+64*68+64*4;
    float* sh_sq =sh_sum+64;
    int tid=threadIdx.x, blk=blockIdx.x;
    for(int e=tid;e<64*67;e+=512){
        int o=e/67, c=e-o*67;
        if(c<3) sh_w3[o][c]=W1[e];
        else    sh_w[o][c-3]=W1[e];
    }
    if(tid<64){ sh_sum[tid]=0.f; sh_sq[tid]=0.f; }
    {
        int r=tid>>2, q=tid&3;          // r 0..127, q: 16 halfs each
        int grp=blk*4+(r>>5);
        int b=grp>>10;
        int i=d_idx[(size_t)grp*SS+(r&31)];
        const uint4* fr=(const uint4*)(d_featTh+((size_t)b*NN+i)*CC)+q*2;
        uint4 u0=fr[0], u1=fr[1];
        float* dst=&sh_x[r][q*16];
        float2 f;
        f=__half22float2(*(__half2*)&u0.x); dst[0]=f.x; dst[1]=f.y;
        f=__half22float2(*(__half2*)&u0.y); dst[2]=f.x; dst[3]=f.y;
        f=__half22float2(*(__half2*)&u0.z); dst[4]=f.x; dst[5]=f.y;
        f=__half22float2(*(__half2*)&u0.w); dst[6]=f.x; dst[7]=f.y;
        f=__half22float2(*(__half2*)&u1.x); dst[8]=f.x; dst[9]=f.y;
        f=__half22float2(*(__half2*)&u1.y); dst[10]=f.x; dst[11]=f.y;
        f=__half22float2(*(__half2*)&u1.z); dst[12]=f.x; dst[13]=f.y;
        f=__half22float2(*(__half2*)&u1.w); dst[14]=f.x; dst[15]=f.y;
        if(q==0){
            const float* xt=d_xyzT+(size_t)b*3*NN;
            const float* cp=d_newxyz+(size_t)grp*3;
            sh_d[r][0]=__fsub_rn(xt[i],      cp[0]);
            sh_d[r][1]=__fsub_rn(xt[NN+i],   cp[1]);
            sh_d[r][2]=__fsub_rn(xt[2*NN+i], cp[2]);
        }
    }
    __syncthreads();
    int w=tid>>5, lane=tid&31, g=lane>>2, t=lane&3;
    int mt=w&7, nh=w>>3;
    int r0=mt*16;
    float acc[4][4];
#pragma unroll
    for(int nt=0;nt<4;nt++){acc[nt][0]=0;acc[nt][1]=0;acc[nt][2]=0;acc[nt][3]=0;}
#pragma unroll
    for(int kt=0;kt<8;kt++){
        int k0=kt*8;
        unsigned a0=f2tf(sh_x[r0+g  ][k0+t  ]);
        unsigned a1=f2tf(sh_x[r0+g+8][k0+t  ]);
        unsigned a2=f2tf(sh_x[r0+g  ][k0+t+4]);
        unsigned a3=f2tf(sh_x[r0+g+8][k0+t+4]);
#pragma unroll
        for(int nt=0;nt<4;nt++){
            int n0=nh*32+nt*8;
            unsigned b0=f2tf(sh_w[n0+g][k0+t  ]);
            unsigned b1=f2tf(sh_w[n0+g][k0+t+4]);
            mma_tf32(acc[nt], a0,a1,a2,a3, b0,b1);
        }
    }
    float dx0=sh_d[r0+g][0],   dy0=sh_d[r0+g][1],   dz0=sh_d[r0+g][2];
    float dx1=sh_d[r0+g+8][0], dy1=sh_d[r0+g+8][1], dz1=sh_d[r0+g+8][2];
#pragma unroll
    for(int nt=0;nt<4;nt++){
        int n0=nh*32+nt*8;
        int col=n0+2*t;
        float wa0=sh_w3[col][0],   wa1=sh_w3[col][1],   wa2=sh_w3[col][2];
        float wb0=sh_w3[col+1][0], wb1=sh_w3[col+1][1], wb2=sh_w3[col+1][2];
        acc[nt][0]+=dx0*wa0+dy0*wa1+dz0*wa2;
        acc[nt][1]+=dx0*wb0+dy0*wb1+dz0*wb2;
        acc[nt][2]+=dx1*wa0+dy1*wa1+dz1*wa2;
        acc[nt][3]+=dx1*wb0+dy1*wb1+dz1*wb2;
        *(__half2*)(d_y1h+((size_t)blk*128+r0+g  )*64+col)=__floats2half2_rn(acc[nt][0],acc[nt][1]);
        *(__half2*)(d_y1h+((size_t)blk*128+r0+g+8)*64+col)=__floats2half2_rn(acc[nt][2],acc[nt][3]);
        float s0=acc[nt][0]+acc[nt][2], s1=acc[nt][1]+acc[nt][3];
        float q0=acc[nt][0]*acc[nt][0]+acc[nt][2]*acc[nt][2];
        float q1=acc[nt][1]*acc[nt][1]+acc[nt][3]*acc[nt][3];
#pragma unroll
        for(int off=4;off<32;off<<=1){
            s0+=__shfl_xor_sync(0xffffffffu,s0,off);
            s1+=__shfl_xor_sync(0xffffffffu,s1,off);
            q0+=__shfl_xor_sync(0xffffffffu,q0,off);
            q1+=__shfl_xor_sync(0xffffffffu,q1,off);
        }
        if(lane<4){
            atomicAdd(&sh_sum[col],s0); atomicAdd(&sh_sum[col+1],s1);
            atomicAdd(&sh_sq[col],q0);  atomicAdd(&sh_sq[col+1],q1);
        }
    }
    __syncthreads();
    if(tid<64){ atomicAdd(&g_s1[tid],(double)sh_sum[tid]); atomicAdd(&g_q1[tid],(double)sh_sq[tid]); }
}

// layer2: fp16 y1 in (BN1+ReLU), tf32 mma, fp16 y2 out, stats
__global__ __launch_bounds__(512) void gemm_l2(const float* __restrict__ W2){
    extern __shared__ float dyn[];
    float (*sh_x)[68]=(float(*)[68])dyn;
    float (*sh_w)[68]=(float(*)[68])(dyn+128*68);
    float* sh_sum=dyn+128*68+64*68;
    float* sh_sq =sh_sum+64;
    int tid=threadIdx.x, blk=blockIdx.x;
    for(int e=tid;e<64*64;e+=512) sh_w[e>>6][e&63]=W2[e];
    if(tid<64){ sh_sum[tid]=0.f; sh_sq[tid]=0.f; }
    {
        int r=tid>>2, q=tid&3;
        const uint4* src=(const uint4*)(d_y1h+((size_t)blk*128+r)*64+q*16);
        uint4 u0=src[0], u1=src[1];
        h8_bn(u0,&sh_x[r][q*16],  g_a1,g_c1,q*16);
        h8_bn(u1,&sh_x[r][q*16+8],g_a1,g_c1,q*16+8);
    }
    __syncthreads();
    int w=tid>>5, lane=tid&31, g=lane>>2, t=lane&3;
    int mt=w&7, nh=w>>3;
    int r0=mt*16;
    float acc[4][4];
#pragma unroll
    for(int nt=0;nt<4;nt++){acc[nt][0]=0;acc[nt][1]=0;acc[nt][2]=0;acc[nt][3]=0;}
#pragma unroll
    for(int kt=0;kt<8;kt++){
        int k0=kt*8;
        unsigned a0=f2tf(sh_x[r0+g  ][k0+t  ]);
        unsigned a1=f2tf(sh_x[r0+g+8][k0+t  ]);
        unsigned a2=f2tf(sh_x[r0+g  ][k0+t+4]);
        unsigned a3=f2tf(sh_x[r0+g+8][k0+t+4]);
#pragma unroll
        for(int nt=0;nt<4;nt++){
            int n0=nh*32+nt*8;
            unsigned b0=f2tf(sh_w[n0+g][k0+t  ]);
            unsigned b1=f2tf(sh_w[n0+g][k0+t+4]);
            mma_tf32(acc[nt], a0,a1,a2,a3, b0,b1);
        }
    }
#pragma unroll
    for(int nt=0;nt<4;nt++){
        int n0=nh*32+nt*8;
        int col=n0+2*t;
        *(__half2*)(d_y2h+((size_t)blk*128+r0+g  )*64+col)=__floats2half2_rn(acc[nt][0],acc[nt][1]);
        *(__half2*)(d_y2h+((size_t)blk*128+r0+g+8)*64+col)=__floats2half2_rn(acc[nt][2],acc[nt][3]);
        float s0=acc[nt][0]+acc[nt][2], s1=acc[nt][1]+acc[nt][3];
        float q0=acc[nt][0]*acc[nt][0]+acc[nt][2]*acc[nt][2];
        float q1=acc[nt][1]*acc[nt][1]+acc[nt][3]*acc[nt][3];
#pragma unroll
        for(int off=4;off<32;off<<=1){
            s0+=__shfl_xor_sync(0xffffffffu,s0,off);
            s1+=__shfl_xor_sync(0xffffffffu,s1,off);
            q0+=__shfl_xor_sync(0xffffffffu,q0,off);
            q1+=__shfl_xor_sync(0xffffffffu,q1,off);
        }
        if(lane<4){
            atomicAdd(&sh_sum[col],s0); atomicAdd(&sh_sum[col+1],s1);
            atomicAdd(&sh_sq[col],q0);  atomicAdd(&sh_sq[col+1],q1);
        }
    }
    __syncthreads();
    if(tid<64){ atomicAdd(&g_s2[tid],(double)sh_sum[tid]); atomicAdd(&g_q2[tid],(double)sh_sq[tid]); }
}

// layer3: fp16 y2 in (BN2+ReLU), tf32 mma, fused stats + pool max
__global__ __launch_bounds__(512) void gemm_l3(const float* __restrict__ W3){
    extern __shared__ float dyn[];
    float (*sh_x)[68]=(float(*)[68])dyn;
    float (*sh_w)[68]=(float(*)[68])(dyn+128*68);
    float* sh_sum=dyn+128*68+128*68;
    float* sh_sq =sh_sum+128;
    unsigned* sh_max=(unsigned*)(sh_sq+128);
    int tid=threadIdx.x, blk=blockIdx.x;
    for(int e=tid;e<128*64;e+=512) sh_w[e>>6][e&63]=W3[e];
    if(tid<128){ sh_sum[tid]=0.f; sh_sq[tid]=0.f; }
    if(tid<512) sh_max[tid]=0u;
    {
        int r=tid>>2, q=tid&3;
        const uint4* src=(const uint4*)(d_y2h+((size_t)blk*128+r)*64+q*16);
        uint4 u0=src[0], u1=src[1];
        h8_bn(u0,&sh_x[r][q*16],  g_a2,g_c2,q*16);
        h8_bn(u1,&sh_x[r][q*16+8],g_a2,g_c2,q*16+8);
    }
    __syncthreads();
    int w=tid>>5, lane=tid&31, g=lane>>2, t=lane&3;
    int mt=w&7, nh=w>>3;
    int r0=mt*16;
    int grp=mt>>1;
    float acc[8][4];
#pragma unroll
    for(int nt=0;nt<8;nt++){acc[nt][0]=0;acc[nt][1]=0;acc[nt][2]=0;acc[nt][3]=0;}
#pragma unroll
    for(int kt=0;kt<8;kt++){
        int k0=kt*8;
        unsigned a0=f2tf(sh_x[r0+g  ][k0+t  ]);
        unsigned a1=f2tf(sh_x[r0+g+8][k0+t  ]);
        unsigned a2=f2tf(sh_x[r0+g  ][k0+t+4]);
        unsigned a3=f2tf(sh_x[r0+g+8][k0+t+4]);
#pragma unroll
        for(int nt=0;nt<8;nt++){
            int n0=nh*64+nt*8;
            unsigned b0=f2tf(sh_w[n0+g][k0+t  ]);
            unsigned b1=f2tf(sh_w[n0+g][k0+t+4]);
            mma_tf32(acc[nt], a0,a1,a2,a3, b0,b1);
        }
    }
#pragma unroll
    for(int nt=0;nt<8;nt++){
        int n0=nh*64+nt*8;
        int col=n0+2*t;
        float s0=acc[nt][0]+acc[nt][2], s1=acc[nt][1]+acc[nt][3];
        float q0=acc[nt][0]*acc[nt][0]+acc[nt][2]*acc[nt][2];
        float q1=acc[nt][1]*acc[nt][1]+acc[nt][3]*acc[nt][3];
        float m0=fmaxf(acc[nt][0],acc[nt][2]), m1=fmaxf(acc[nt][1],acc[nt][3]);
#pragma unroll
        for(int off=4;off<32;off<<=1){
            s0+=__shfl_xor_sync(0xffffffffu,s0,off);
            s1+=__shfl_xor_sync(0xffffffffu,s1,off);
            q0+=__shfl_xor_sync(0xffffffffu,q0,off);
            q1+=__shfl_xor_sync(0xffffffffu,q1,off);
            m0=fmaxf(m0,__shfl_xor_sync(0xffffffffu,m0,off));
            m1=fmaxf(m1,__shfl_xor_sync(0xffffffffu,m1,off));
        }
        if(lane<4){
            atomicAdd(&sh_sum[col],s0); atomicAdd(&sh_sum[col+1],s1);
            atomicAdd(&sh_sq[col],q0);  atomicAdd(&sh_sq[col+1],q1);
            atomicMax(&sh_max[grp*128+col],fkey(m0));
            atomicMax(&sh_max[grp*128+col+1],fkey(m1));
        }
    }
    __syncthreads();
    if(tid<128){
        atomicAdd(&g_s3[tid],(double)sh_sum[tid]);
        atomicAdd(&g_q3[tid],(double)sh_sq[tid]);
    }
    if(tid<512)
        d_m3[((size_t)blk*4+(tid>>7))*128+(tid&127)]=finv(sh_max[tid]);
}

__global__ void final_kernel(float* __restrict__ outf){
    __shared__ float t[32][33];
    int b=blockIdx.z, o0=blockIdx.y*32, p0=blockIdx.x*32;
#pragma unroll
    for(int k=0;k<32;k+=8){
        int p=p0+threadIdx.y+k, o=o0+threadIdx.x;
        float v=d_m3[((size_t)b*PP+p)*128+o];
        t[threadIdx.y+k][threadIdx.x]=fmaxf(fmaf(g_a3[o],v,g_c3[o]),0.f);
    }
    __syncthreads();
#pragma unroll
    for(int k=0;k<32;k+=8){
        int o=o0+threadIdx.y+k;
        outf[((size_t)b*128+o)*PP+p0+threadIdx.x]=t[threadIdx.x][threadIdx.y+k];
    }
}

extern "C" void kernel_launch(void* const* d_in, const int* in_sizes, int n_in,
                              void* d_out, int out_size){
    const float* xyz =(const float*)d_in[0];
    const float* feat=(const float*)d_in[1];
    const float* W1  =(const float*)d_in[2];
    const float* g1  =(const float*)d_in[3];
    const float* b1  =(const float*)d_in[4];
    const float* W2  =(const float*)d_in[5];
    const float* g2  =(const float*)d_in[6];
    const float* b2  =(const float*)d_in[7];
    const float* W3  =(const float*)d_in[8];
    const float* g3  =(const float*)d_in[9];
    const float* b3  =(const float*)d_in[10];
    float* out=(float*)d_out;
    float* out_newxyz=out;
    float* out_feat  =out+(size_t)BB*PP*3;

    static int init_done=0;
    if(!init_done){
        cudaFuncSetAttribute(gemm_l1, cudaFuncAttributeMaxDynamicSharedMemorySize, SMEM_L1T);
        cudaFuncSetAttribute(gemm_l2, cudaFuncAttributeMaxDynamicSharedMemorySize, SMEM_L2T);
        cudaFuncSetAttribute(gemm_l3, cudaFuncAttributeMaxDynamicSharedMemorySize, SMEM_L3T);
        init_done=1;
    }

    zero_stats<<<1,128>>>();
    {
        dim3 g(NN/32, CC/32, BB), b(32,8);
        transpose_feat<<<g,b>>>(feat);
    }
    {
        dim3 g(NN/256, BB);
        xyz_soa<<<g,256>>>(xyz);
    }
    fps_kernel<<<BB,256>>>(xyz, out_newxyz);
    ballq_kernel<<<(BB*PP)/4,128>>>();
    gemm_l1<<<NROWS/128,512,SMEM_L1T>>>(W1);
    mkscale_kernel<<<1,128>>>(g1,b1,1,64);
    gemm_l2<<<NROWS/128,512,SMEM_L2T>>>(W2);
    mkscale_kernel<<<1,128>>>(g2,b2,2,64);
    gemm_l3<<<NROWS/128,512,SMEM_L3T>>>(W3);
    mkscale_kernel<<<1,128>>>(g3,b3,3,128);
    {
        dim3 g(PP/32, 128/32, BB), b(32,8);
        final_kernel<<<g,b>>>(out_feat);
    }
}

// round 17
// speedup vs baseline: 1.1872x; 1.0100x over previous
#include <cuda_runtime.h>
#include <cuda_fp16.h>
#include <math.h>

#define BB 16
#define NN 4096
#define CC 64
#define PP 1024
#define SS 32
#define NROWS (BB*PP*SS)   // 524288

__device__ __half  d_featTh[(size_t)BB*NN*CC];
__device__ float   d_xyzT[(size_t)BB*3*NN];
__device__ float   d_newxyz[BB*PP*3];
__device__ int     d_idx[BB*PP*SS];
__device__ __half  d_y1h[(size_t)NROWS*64];
__device__ __half  d_y2h[(size_t)NROWS*64];
__device__ float   d_m3[(size_t)BB*PP*128];
__device__ double  g_s1[64], g_q1[64], g_s2[64], g_q2[64], g_s3[128], g_q3[128];
__device__ float   g_a1[64], g_c1[64], g_a2[64], g_c2[64], g_a3[128], g_c3[128];

__device__ __forceinline__ float sqdist(float ax,float ay,float az,float bx,float by,float bz){
    float dx=__fsub_rn(ax,bx), dy=__fsub_rn(ay,by), dz=__fsub_rn(az,bz);
    return __fadd_rn(__fadd_rn(__fmul_rn(dx,dx),__fmul_rn(dy,dy)),__fmul_rn(dz,dz));
}
__device__ __forceinline__ unsigned fkey(float f){
    unsigned u=__float_as_uint(f); return (u&0x80000000u)?~u:(u|0x80000000u);
}
__device__ __forceinline__ float finv(unsigned k){
    unsigned u=(k&0x80000000u)?(k&0x7fffffffu):~k; return __uint_as_float(u);
}
__device__ __forceinline__ unsigned long long pk2(float a,float b){
    unsigned long long r; asm("mov.b64 %0,{%1,%2};" : "=l"(r) : "f"(a),"f"(b)); return r;
}
__device__ __forceinline__ void upk2(unsigned long long v,float&a,float&b){
    asm("mov.b64 {%0,%1},%2;" : "=f"(a),"=f"(b) : "l"(v));
}
__device__ __forceinline__ unsigned long long add2(unsigned long long a,unsigned long long b){
    unsigned long long r; asm("add.rn.f32x2 %0,%1,%2;" : "=l"(r) : "l"(a),"l"(b)); return r;
}
__device__ __forceinline__ unsigned long long mul2(unsigned long long a,unsigned long long b){
    unsigned long long r; asm("mul.rn.f32x2 %0,%1,%2;" : "=l"(r) : "l"(a),"l"(b)); return r;
}
__device__ __forceinline__ unsigned f2tf(float f){
    unsigned r; asm("cvt.rna.tf32.f32 %0,%1;" : "=r"(r) : "f"(f)); return r;
}
__device__ __forceinline__ void mma_tf32(float* c, unsigned a0,unsigned a1,unsigned a2,unsigned a3,
                                         unsigned b0,unsigned b1){
    asm("mma.sync.aligned.m16n8k8.row.col.f32.tf32.tf32.f32 "
        "{%0,%1,%2,%3},{%4,%5,%6,%7},{%8,%9},{%0,%1,%2,%3};"
        : "+f"(c[0]),"+f"(c[1]),"+f"(c[2]),"+f"(c[3])
        : "r"(a0),"r"(a1),"r"(a2),"r"(a3),"r"(b0),"r"(b1));
}

// ---- fused: fps (blocks 0..15) + transpose_feat (16..4111) + xyz_soa (4112..4367) + zero_stats (4368)
#define PRE_GRID (16+4096+256+1)
__global__ __launch_bounds__(256,1) void pre_kernel(const float* __restrict__ xyz,
                                                    const float* __restrict__ feat,
                                                    float* __restrict__ out_newxyz){
    __shared__ float sh_buf[32*33];         // transpose tile / xyz staging
    __shared__ unsigned s_d[2][8];
    __shared__ unsigned s_i[2][8];
    int bid=blockIdx.x, tid=threadIdx.x;

    if(bid>=16){
        int t=bid-16;
        if(t<4096){
            // transpose feat tile: (B,64,N) fp32 -> (B,N,64) fp16
            int b=t>>8, r=t&255;
            int c0=(r>>7)*32, n0=(r&127)*32;
            int tx=tid&31, ty=tid>>5;
            float (*tt)[33]=(float(*)[33])sh_buf;
            const float* src=feat+((size_t)b*CC+c0)*NN+n0;
#pragma unroll
            for(int k=0;k<32;k+=8)
                tt[ty+k][tx]=src[(size_t)(ty+k)*NN+tx];
            __syncthreads();
            __half* dst=d_featTh+((size_t)b*NN+n0)*CC+c0;
#pragma unroll
            for(int k=0;k<32;k+=8)
                dst[(size_t)(ty+k)*CC+tx]=__float2half_rn(tt[tx][ty+k]);
        } else if(t<4352){
            int t2=t-4096;
            int b=t2>>4, n0=(t2&15)*256;
            const float* src=xyz+((size_t)b*NN+n0)*3;
            for(int k=tid;k<768;k+=256) sh_buf[k]=src[k];
            __syncthreads();
            float* dst=d_xyzT+(size_t)b*3*NN;
            int n=n0+tid;
            dst[n]      =sh_buf[tid*3+0];
            dst[NN+n]   =sh_buf[tid*3+1];
            dst[2*NN+n] =sh_buf[tid*3+2];
        } else {
            if(tid<64){g_s1[tid]=0.0;g_q1[tid]=0.0;g_s2[tid]=0.0;g_q2[tid]=0.0;}
            if(tid<128){g_s3[tid]=0.0;g_q3[tid]=0.0;}
        }
        return;
    }

    // ---- FPS block ----
    int b=bid;
    int warp=tid>>5, lane=tid&31;
    const float* X=xyz+(size_t)b*NN*3;
    unsigned long long px2[8],py2[8],pz2[8];
    float dd[16];
#pragma unroll
    for(int jj=0;jj<8;jj++){
        int p0=tid+(2*jj)*256, p1=tid+(2*jj+1)*256;
        px2[jj]=pk2(X[p0*3+0],X[p1*3+0]);
        py2[jj]=pk2(X[p0*3+1],X[p1*3+1]);
        pz2[jj]=pk2(X[p0*3+2],X[p1*3+2]);
        dd[2*jj]=1e10f; dd[2*jj+1]=1e10f;
    }
    if(tid<8){ s_d[0][tid]=0u; s_d[1][tid]=0u; s_i[0][tid]=0xFFFFFFFFu; s_i[1][tid]=0xFFFFFFFFu; }
    float lx=__ldg(&X[0]), ly=__ldg(&X[1]), lz=__ldg(&X[2]);
    if(tid==0){
        float* o1=d_newxyz+(size_t)b*PP*3; o1[0]=lx;o1[1]=ly;o1[2]=lz;
        float* o2=out_newxyz+(size_t)b*PP*3; o2[0]=lx;o2[1]=ly;o2[2]=lz;
    }
    __syncthreads();
    for(int it=1; it<PP; it++){
        int p=it&1;
        unsigned long long nx=pk2(-lx,-lx), ny=pk2(-ly,-ly), nz=pk2(-lz,-lz);
#pragma unroll
        for(int jj=0;jj<8;jj++){
            unsigned long long dx=add2(px2[jj],nx);
            unsigned long long dy=add2(py2[jj],ny);
            unsigned long long dz=add2(pz2[jj],nz);
            unsigned long long s=add2(add2(mul2(dx,dx),mul2(dy,dy)),mul2(dz,dz));
            float d0,d1; upk2(s,d0,d1);
            dd[2*jj]=fminf(dd[2*jj],d0);
            dd[2*jj+1]=fminf(dd[2*jj+1],d1);
        }
        float m=dd[0];
#pragma unroll
        for(int j=1;j<16;j++) m=fmaxf(m,dd[j]);
        unsigned cand=0xFFFFFFFFu;
#pragma unroll
        for(int j=15;j>=0;j--) if(dd[j]==m) cand=tid+(unsigned)(j*256);
        unsigned mb=__float_as_uint(m);
        unsigned wmax=__reduce_max_sync(0xffffffffu, mb);
        unsigned wi=__reduce_min_sync(0xffffffffu, (mb==wmax)?cand:0xFFFFFFFFu);
        if(lane==0){ s_d[p][warp]=wmax; s_i[p][warp]=wi; }
        __syncthreads();
        unsigned dv=(lane<8)?s_d[p][lane]:0u;
        unsigned iv=(lane<8)?s_i[p][lane]:0xFFFFFFFFu;
        unsigned bmax=__reduce_max_sync(0xffffffffu, dv);
        unsigned widx=__reduce_min_sync(0xffffffffu, (dv==bmax)?iv:0xFFFFFFFFu);
        lx=__ldg(&X[widx*3+0]);
        ly=__ldg(&X[widx*3+1]);
        lz=__ldg(&X[widx*3+2]);
        if(tid==0){
            float* o1=d_newxyz+((size_t)b*PP+it)*3; o1[0]=lx;o1[1]=ly;o1[2]=lz;
            float* o2=out_newxyz+((size_t)b*PP+it)*3; o2[0]=lx;o2[1]=ly;o2[2]=lz;
        }
    }
}

__global__ __launch_bounds__(128) void ballq_kernel(){
    int warp=blockIdx.x*4+(threadIdx.x>>5);
    int lane=threadIdx.x&31;
    int b=warp>>10;
    const float* Xx=d_xyzT+(size_t)b*3*NN;
    const float* Xy=Xx+NN;
    const float* Xz=Xx+2*NN;
    float cx=d_newxyz[warp*3+0], cy=d_newxyz[warp*3+1], cz=d_newxyz[warp*3+2];
    int* out=d_idx+(size_t)warp*SS;
    const float R2=0.04f;
    int cnt=0, firstIdx=-1;
    for(int base=0; base<NN && cnt<SS; base+=32){
        int n=base+lane;
        bool in=sqdist(cx,cy,cz,Xx[n],Xy[n],Xz[n])<R2;
        unsigned m=__ballot_sync(0xffffffffu,in);
        if(firstIdx<0 && m) firstIdx=base+__ffs(m)-1;
        if(in){
            int pos=cnt+__popc(m&((1u<<lane)-1u));
            if(pos<SS) out[pos]=n;
        }
        cnt+=__popc(m);
    }
    int written=cnt<SS?cnt:SS;
    if(lane>=written) out[lane]=firstIdx;
}

__global__ void mkscale_kernel(const float* __restrict__ g, const float* __restrict__ bb,
                               int layer, int Cn){
    int o=threadIdx.x;
    if(o>=Cn) return;
    const double inv=1.0/(double)NROWS;
    double s,q;
    if(layer==1){s=g_s1[o];q=g_q1[o];}
    else if(layer==2){s=g_s2[o];q=g_q2[o];}
    else {s=g_s3[o];q=g_q3[o];}
    double m=s*inv, v=q*inv-m*m;
    double aa=(double)g[o]/sqrt(v+1e-5);
    float af=(float)aa, cf=(float)((double)bb[o]-m*aa);
    if(layer==1){g_a1[o]=af;g_c1[o]=cf;}
    else if(layer==2){g_a2[o]=af;g_c2[o]=cf;}
    else {g_a3[o]=af;g_c3[o]=cf;}
}

#define SMEM_L1T ((128*68 + 128*4 + 64*68 + 64*4 + 128)*4)
#define SMEM_L2T ((128*68 + 64*68 + 128)*4)
#define SMEM_L3T ((128*68 + 128*68 + 256 + 512)*4)

__device__ __forceinline__ void h8_bn(uint4 u,float* dst,const float* ga,const float* gc,int c0){
    float2 f;
    f=__half22float2(*(__half2*)&u.x);
    dst[0]=fmaxf(fmaf(ga[c0+0],f.x,gc[c0+0]),0.f);
    dst[1]=fmaxf(fmaf(ga[c0+1],f.y,gc[c0+1]),0.f);
    f=__half22float2(*(__half2*)&u.y);
    dst[2]=fmaxf(fmaf(ga[c0+2],f.x,gc[c0+2]),0.f);
    dst[3]=fmaxf(fmaf(ga[c0+3],f.y,gc[c0+3]),0.f);
    f=__half22float2(*(__half2*)&u.z);
    dst[4]=fmaxf(fmaf(ga[c0+4],f.x,gc[c0+4]),0.f);
    dst[5]=fmaxf(fmaf(ga[c0+5],f.y,gc[c0+5]),0.f);
    f=__half22float2(*(__half2*)&u.w);
    dst[6]=fmaxf(fmaf(ga[c0+6],f.x,gc[c0+6]),0.f);
    dst[7]=fmaxf(fmaf(ga[c0+7],f.y,gc[c0+7]),0.f);
}

__global__ __launch_bounds__(512) void gemm_l1(const float* __restrict__ W1){
    extern __shared__ float dyn[];
    float (*sh_x)[68]=(float(*)[68])dyn;
    float (*sh_d)[4] =(float(*)[4])(dyn+128*68);
    float (*sh_w)[68]=(float(*)[68])(dyn+128*68+128*4);
    float (*sh_w3)[4]=(float(*)[4])(dyn+128*68+128*4+64*68);
    float* sh_sum=dyn+128*68+128*4+64*68+64*4;
    float* sh_sq =sh_sum+64;
    int tid=threadIdx.x, blk=blockIdx.x;
    for(int e=tid;e<64*67;e+=512){
        int o=e/67, c=e-o*67;
        if(c<3) sh_w3[o][c]=W1[e];
        else    sh_w[o][c-3]=W1[e];
    }
    if(tid<64){ sh_sum[tid]=0.f; sh_sq[tid]=0.f; }
    {
        int r=tid>>2, q=tid&3;
        int grp=blk*4+(r>>5);
        int b=grp>>10;
        int i=d_idx[(size_t)grp*SS+(r&31)];
        const uint4* fr=(const uint4*)(d_featTh+((size_t)b*NN+i)*CC)+q*2;
        uint4 u0=fr[0], u1=fr[1];
        float* dst=&sh_x[r][q*16];
        float2 f;
        f=__half22float2(*(__half2*)&u0.x); dst[0]=f.x; dst[1]=f.y;
        f=__half22float2(*(__half2*)&u0.y); dst[2]=f.x; dst[3]=f.y;
        f=__half22float2(*(__half2*)&u0.z); dst[4]=f.x; dst[5]=f.y;
        f=__half22float2(*(__half2*)&u0.w); dst[6]=f.x; dst[7]=f.y;
        f=__half22float2(*(__half2*)&u1.x); dst[8]=f.x; dst[9]=f.y;
        f=__half22float2(*(__half2*)&u1.y); dst[10]=f.x; dst[11]=f.y;
        f=__half22float2(*(__half2*)&u1.z); dst[12]=f.x; dst[13]=f.y;
        f=__half22float2(*(__half2*)&u1.w); dst[14]=f.x; dst[15]=f.y;
        if(q==0){
            const float* xt=d_xyzT+(size_t)b*3*NN;
            const float* cp=d_newxyz+(size_t)grp*3;
            sh_d[r][0]=__fsub_rn(xt[i],      cp[0]);
            sh_d[r][1]=__fsub_rn(xt[NN+i],   cp[1]);
            sh_d[r][2]=__fsub_rn(xt[2*NN+i], cp[2]);
        }
    }
    __syncthreads();
    int w=tid>>5, lane=tid&31, g=lane>>2, t=lane&3;
    int mt=w&7, nh=w>>3;
    int r0=mt*16;
    float acc[4][4];
#pragma unroll
    for(int nt=0;nt<4;nt++){acc[nt][0]=0;acc[nt][1]=0;acc[nt][2]=0;acc[nt][3]=0;}
#pragma unroll
    for(int kt=0;kt<8;kt++){
        int k0=kt*8;
        unsigned a0=f2tf(sh_x[r0+g  ][k0+t  ]);
        unsigned a1=f2tf(sh_x[r0+g+8][k0+t  ]);
        unsigned a2=f2tf(sh_x[r0+g  ][k0+t+4]);
        unsigned a3=f2tf(sh_x[r0+g+8][k0+t+4]);
#pragma unroll
        for(int nt=0;nt<4;nt++){
            int n0=nh*32+nt*8;
            unsigned b0=f2tf(sh_w[n0+g][k0+t  ]);
            unsigned b1=f2tf(sh_w[n0+g][k0+t+4]);
            mma_tf32(acc[nt], a0,a1,a2,a3, b0,b1);
        }
    }
    float dx0=sh_d[r0+g][0],   dy0=sh_d[r0+g][1],   dz0=sh_d[r0+g][2];
    float dx1=sh_d[r0+g+8][0], dy1=sh_d[r0+g+8][1], dz1=sh_d[r0+g+8][2];
#pragma unroll
    for(int nt=0;nt<4;nt++){
        int n0=nh*32+nt*8;
        int col=n0+2*t;
        float wa0=sh_w3[col][0],   wa1=sh_w3[col][1],   wa2=sh_w3[col][2];
        float wb0=sh_w3[col+1][0], wb1=sh_w3[col+1][1], wb2=sh_w3[col+1][2];
        acc[nt][0]+=dx0*wa0+dy0*wa1+dz0*wa2;
        acc[nt][1]+=dx0*wb0+dy0*wb1+dz0*wb2;
        acc[nt][2]+=dx1*wa0+dy1*wa1+dz1*wa2;
        acc[nt][3]+=dx1*wb0+dy1*wb1+dz1*wb2;
        *(__half2*)(d_y1h+((size_t)blk*128+r0+g  )*64+col)=__floats2half2_rn(acc[nt][0],acc[nt][1]);
        *(__half2*)(d_y1h+((size_t)blk*128+r0+g+8)*64+col)=__floats2half2_rn(acc[nt][2],acc[nt][3]);
        float s0=acc[nt][0]+acc[nt][2], s1=acc[nt][1]+acc[nt][3];
        float q0=acc[nt][0]*acc[nt][0]+acc[nt][2]*acc[nt][2];
        float q1=acc[nt][1]*acc[nt][1]+acc[nt][3]*acc[nt][3];
#pragma unroll
        for(int off=4;off<32;off<<=1){
            s0+=__shfl_xor_sync(0xffffffffu,s0,off);
            s1+=__shfl_xor_sync(0xffffffffu,s1,off);
            q0+=__shfl_xor_sync(0xffffffffu,q0,off);
            q1+=__shfl_xor_sync(0xffffffffu,q1,off);
        }
        if(lane<4){
            atomicAdd(&sh_sum[col],s0); atomicAdd(&sh_sum[col+1],s1);
            atomicAdd(&sh_sq[col],q0);  atomicAdd(&sh_sq[col+1],q1);
        }
    }
    __syncthreads();
    if(tid<64){ atomicAdd(&g_s1[tid],(double)sh_sum[tid]); atomicAdd(&g_q1[tid],(double)sh_sq[tid]); }
}

__global__ __launch_bounds__(512) void gemm_l2(const float* __restrict__ W2){
    extern __shared__ float dyn[];
    float (*sh_x)[68]=(float(*)[68])dyn;
    float (*sh_w)[68]=(float(*)[68])(dyn+128*68);
    float* sh_sum=dyn+128*68+64*68;
    float* sh_sq =sh_sum+64;
    int tid=threadIdx.x, blk=blockIdx.x;
    for(int e=tid;e<64*64;e+=512) sh_w[e>>6][e&63]=W2[e];
    if(tid<64){ sh_sum[tid]=0.f; sh_sq[tid]=0.f; }
    {
        int r=tid>>2, q=tid&3;
        const uint4* src=(const uint4*)(d_y1h+((size_t)blk*128+r)*64+q*16);
        uint4 u0=src[0], u1=src[1];
        h8_bn(u0,&sh_x[r][q*16],  g_a1,g_c1,q*16);
        h8_bn(u1,&sh_x[r][q*16+8],g_a1,g_c1,q*16+8);
    }
    __syncthreads();
    int w=tid>>5, lane=tid&31, g=lane>>2, t=lane&3;
    int mt=w&7, nh=w>>3;
    int r0=mt*16;
    float acc[4][4];
#pragma unroll
    for(int nt=0;nt<4;nt++){acc[nt][0]=0;acc[nt][1]=0;acc[nt][2]=0;acc[nt][3]=0;}
#pragma unroll
    for(int kt=0;kt<8;kt++){
        int k0=kt*8;
        unsigned a0=f2tf(sh_x[r0+g  ][k0+t  ]);
        unsigned a1=f2tf(sh_x[r0+g+8][k0+t  ]);
        unsigned a2=f2tf(sh_x[r0+g  ][k0+t+4]);
        unsigned a3=f2tf(sh_x[r0+g+8][k0+t+4]);
#pragma unroll
        for(int nt=0;nt<4;nt++){
            int n0=nh*32+nt*8;
            unsigned b0=f2tf(sh_w[n0+g][k0+t  ]);
            unsigned b1=f2tf(sh_w[n0+g][k0+t+4]);
            mma_tf32(acc[nt], a0,a1,a2,a3, b0,b1);
        }
    }
#pragma unroll
    for(int nt=0;nt<4;nt++){
        int n0=nh*32+nt*8;
        int col=n0+2*t;
        *(__half2*)(d_y2h+((size_t)blk*128+r0+g  )*64+col)=__floats2half2_rn(acc[nt][0],acc[nt][1]);
        *(__half2*)(d_y2h+((size_t)blk*128+r0+g+8)*64+col)=__floats2half2_rn(acc[nt][2],acc[nt][3]);
        float s0=acc[nt][0]+acc[nt][2], s1=acc[nt][1]+acc[nt][3];
        float q0=acc[nt][0]*acc[nt][0]+acc[nt][2]*acc[nt][2];
        float q1=acc[nt][1]*acc[nt][1]+acc[nt][3]*acc[nt][3];
#pragma unroll
        for(int off=4;off<32;off<<=1){
            s0+=__shfl_xor_sync(0xffffffffu,s0,off);
            s1+=__shfl_xor_sync(0xffffffffu,s1,off);
            q0+=__shfl_xor_sync(0xffffffffu,q0,off);
            q1+=__shfl_xor_sync(0xffffffffu,q1,off);
        }
        if(lane<4){
            atomicAdd(&sh_sum[col],s0); atomicAdd(&sh_sum[col+1],s1);
            atomicAdd(&sh_sq[col],q0);  atomicAdd(&sh_sq[col+1],q1);
        }
    }
    __syncthreads();
    if(tid<64){ atomicAdd(&g_s2[tid],(double)sh_sum[tid]); atomicAdd(&g_q2[tid],(double)sh_sq[tid]); }
}

__global__ __launch_bounds__(512) void gemm_l3(const float* __restrict__ W3){
    extern __shared__ float dyn[];
    float (*sh_x)[68]=(float(*)[68])dyn;
    float (*sh_w)[68]=(float(*)[68])(dyn+128*68);
    float* sh_sum=dyn+128*68+128*68;
    float* sh_sq =sh_sum+128;
    unsigned* sh_max=(unsigned*)(sh_sq+128);
    int tid=threadIdx.x, blk=blockIdx.x;
    for(int e=tid;e<128*64;e+=512) sh_w[e>>6][e&63]=W3[e];
    if(tid<128){ sh_sum[tid]=0.f; sh_sq[tid]=0.f; }
    if(tid<512) sh_max[tid]=0u;
    {
        int r=tid>>2, q=tid&3;
        const uint4* src=(const uint4*)(d_y2h+((size_t)blk*128+r)*64+q*16);
        uint4 u0=src[0], u1=src[1];
        h8_bn(u0,&sh_x[r][q*16],  g_a2,g_c2,q*16);
        h8_bn(u1,&sh_x[r][q*16+8],g_a2,g_c2,q*16+8);
    }
    __syncthreads();
    int w=tid>>5, lane=tid&31, g=lane>>2, t=lane&3;
    int mt=w&7, nh=w>>3;
    int r0=mt*16;
    int grp=mt>>1;
    float acc[8][4];
#pragma unroll
    for(int nt=0;nt<8;nt++){acc[nt][0]=0;acc[nt][1]=0;acc[nt][2]=0;acc[nt][3]=0;}
#pragma unroll
    for(int kt=0;kt<8;kt++){
        int k0=kt*8;
        unsigned a0=f2tf(sh_x[r0+g  ][k0+t  ]);
        unsigned a1=f2tf(sh_x[r0+g+8][k0+t  ]);
        unsigned a2=f2tf(sh_x[r0+g  ][k0+t+4]);
        unsigned a3=f2tf(sh_x[r0+g+8][k0+t+4]);
#pragma unroll
        for(int nt=0;nt<8;nt++){
            int n0=nh*64+nt*8;
            unsigned b0=f2tf(sh_w[n0+g][k0+t  ]);
            unsigned b1=f2tf(sh_w[n0+g][k0+t+4]);
            mma_tf32(acc[nt], a0,a1,a2,a3, b0,b1);
        }
    }
#pragma unroll
    for(int nt=0;nt<8;nt++){
        int n0=nh*64+nt*8;
        int col=n0+2*t;
        float s0=acc[nt][0]+acc[nt][2], s1=acc[nt][1]+acc[nt][3];
        float q0=acc[nt][0]*acc[nt][0]+acc[nt][2]*acc[nt][2];
        float q1=acc[nt][1]*acc[nt][1]+acc[nt][3]*acc[nt][3];
        float m0=fmaxf(acc[nt][0],acc[nt][2]), m1=fmaxf(acc[nt][1],acc[nt][3]);
#pragma unroll
        for(int off=4;off<32;off<<=1){
            s0+=__shfl_xor_sync(0xffffffffu,s0,off);
            s1+=__shfl_xor_sync(0xffffffffu,s1,off);
            q0+=__shfl_xor_sync(0xffffffffu,q0,off);
            q1+=__shfl_xor_sync(0xffffffffu,q1,off);
            m0=fmaxf(m0,__shfl_xor_sync(0xffffffffu,m0,off));
            m1=fmaxf(m1,__shfl_xor_sync(0xffffffffu,m1,off));
        }
        if(lane<4){
            atomicAdd(&sh_sum[col],s0); atomicAdd(&sh_sum[col+1],s1);
            atomicAdd(&sh_sq[col],q0);  atomicAdd(&sh_sq[col+1],q1);
            atomicMax(&sh_max[grp*128+col],fkey(m0));
            atomicMax(&sh_max[grp*128+col+1],fkey(m1));
        }
    }
    __syncthreads();
    if(tid<128){
        atomicAdd(&g_s3[tid],(double)sh_sum[tid]);
        atomicAdd(&g_q3[tid],(double)sh_sq[tid]);
    }
    if(tid<512)
        d_m3[((size_t)blk*4+(tid>>7))*128+(tid&127)]=finv(sh_max[tid]);
}

__global__ void final_kernel(float* __restrict__ outf){
    __shared__ float t[32][33];
    int b=blockIdx.z, o0=blockIdx.y*32, p0=blockIdx.x*32;
#pragma unroll
    for(int k=0;k<32;k+=8){
        int p=p0+threadIdx.y+k, o=o0+threadIdx.x;
        float v=d_m3[((size_t)b*PP+p)*128+o];
        t[threadIdx.y+k][threadIdx.x]=fmaxf(fmaf(g_a3[o],v,g_c3[o]),0.f);
    }
    __syncthreads();
#pragma unroll
    for(int k=0;k<32;k+=8){
        int o=o0+threadIdx.y+k;
        outf[((size_t)b*128+o)*PP+p0+threadIdx.x]=t[threadIdx.x][threadIdx.y+k];
    }
}

extern "C" void kernel_launch(void* const* d_in, const int* in_sizes, int n_in,
                              void* d_out, int out_size){
    const float* xyz =(const float*)d_in[0];
    const float* feat=(const float*)d_in[1];
    const float* W1  =(const float*)d_in[2];
    const float* g1  =(const float*)d_in[3];
    const float* b1  =(const float*)d_in[4];
    const float* W2  =(const float*)d_in[5];
    const float* g2  =(const float*)d_in[6];
    const float* b2  =(const float*)d_in[7];
    const float* W3  =(const float*)d_in[8];
    const float* g3  =(const float*)d_in[9];
    const float* b3  =(const float*)d_in[10];
    float* out=(float*)d_out;
    float* out_newxyz=out;
    float* out_feat  =out+(size_t)BB*PP*3;

    static int init_done=0;
    if(!init_done){
        cudaFuncSetAttribute(gemm_l1, cudaFuncAttributeMaxDynamicSharedMemorySize, SMEM_L1T);
        cudaFuncSetAttribute(gemm_l2, cudaFuncAttributeMaxDynamicSharedMemorySize, SMEM_L2T);
        cudaFuncSetAttribute(gemm_l3, cudaFuncAttributeMaxDynamicSharedMemorySize, SMEM_L3T);
        init_done=1;
    }

    pre_kernel<<<PRE_GRID,256>>>(xyz, feat, out_newxyz);
    ballq_kernel<<<(BB*PP)/4,128>>>();
    gemm_l1<<<NROWS/128,512,SMEM_L1T>>>(W1);
    mkscale_kernel<<<1,128>>>(g1,b1,1,64);
    gemm_l2<<<NROWS/128,512,SMEM_L2T>>>(W2);
    mkscale_kernel<<<1,128>>>(g2,b2,2,64);
    gemm_l3<<<NROWS/128,512,SMEM_L3T>>>(W3);
    mkscale_kernel<<<1,128>>>(g3,b3,3,128);
    {
        dim3 g(PP/32, 128/32, BB), b(32,8);
        final_kernel<<<g,b>>>(out_feat);
    }
}